// round 16
// baseline (speedup 1.0000x reference)
#include <cuda_runtime.h>
#include <cuda_fp16.h>
#include <cstdint>
#include <cstddef>

#define NB 8
#define NN 2048
#define FD 128

// ---------------- device scratch (no cudaMalloc allowed) ----------------
__device__ float g_dis[NB * NN];
__device__ __half g_Ah[(size_t)NB * NN * NN];   // fp16(dis[n]*adj[n,m])
__device__ __half g_HhA[NB * FD * NN];          // H transposed [b][f][m], buffer A
__device__ __half g_HhB[NB * FD * NN];          // buffer B
__device__ __half g_Xh1[NB * NN * FD];          // fp16 X1 (for residual)
__device__ float g_Wr[3 * FD * FD];             // tf32 weights (layer-0 small GEMM)
__device__ __half g_Wh[2][FD * FD];             // fp16 W^T for W2, W3: [fo][fi]

// ---------------- helpers ----------------
__device__ __forceinline__ uint32_t cvt_rna(float x) {
    uint32_t r;
    asm("cvt.rna.tf32.f32 %0, %1;" : "=r"(r) : "f"(x));
    return r;
}
__device__ __forceinline__ void cp16(uint32_t smem_dst, const void* gsrc) {
    asm volatile("cp.async.cg.shared.global [%0], [%1], 16;" :: "r"(smem_dst), "l"(gsrc));
}
#define SWZ128(o) ((o) ^ (((o) >> 3) & 0x70))

#define LDSM4(R, a) \
    asm volatile("ldmatrix.sync.aligned.m8n8.x4.shared.b16 {%0,%1,%2,%3}, [%4];" \
        : "=r"((R)[0]), "=r"((R)[1]), "=r"((R)[2]), "=r"((R)[3]) : "r"(a))

__device__ __forceinline__ void mma_f16(float* c, const uint32_t* a, const uint32_t* b) {
    asm volatile(
        "mma.sync.aligned.m16n8k16.row.col.f32.f16.f16.f32 "
        "{%0,%1,%2,%3}, {%4,%5,%6,%7}, {%8,%9}, {%0,%1,%2,%3};"
        : "+f"(c[0]), "+f"(c[1]), "+f"(c[2]), "+f"(c[3])
        : "r"(a[0]), "r"(a[1]), "r"(a[2]), "r"(a[3]), "r"(b[0]), "r"(b[1]));
}
__device__ __forceinline__ void mma8(float* c, const uint32_t* a, const uint32_t* b) {
    asm volatile(
        "mma.sync.aligned.m16n8k8.row.col.f32.tf32.tf32.f32 "
        "{%0,%1,%2,%3}, {%4,%5,%6,%7}, {%8,%9}, {%0,%1,%2,%3};"
        : "+f"(c[0]), "+f"(c[1]), "+f"(c[2]), "+f"(c[3])
        : "r"(a[0]), "r"(a[1]), "r"(a[2]), "r"(a[3]), "r"(b[0]), "r"(b[1]));
}

// ---------------- prep: rowsum -> dis -> write fp16 dis*adj ----------------
__global__ void k_prep(const float* __restrict__ adj) {
    __shared__ float red[8];
    __shared__ float sdis;
    int row = blockIdx.x;
    const float4* p = (const float4*)(adj + (size_t)row * NN);
    float s = 0.f;
    for (int i = threadIdx.x; i < NN / 4; i += 256) {
        float4 v = p[i];
        s += (v.x + v.y) + (v.z + v.w);
    }
    #pragma unroll
    for (int o = 16; o > 0; o >>= 1) s += __shfl_xor_sync(0xffffffffu, s, o);
    if ((threadIdx.x & 31) == 0) red[threadIdx.x >> 5] = s;
    __syncthreads();
    if (threadIdx.x < 8) {
        s = red[threadIdx.x];
        #pragma unroll
        for (int o = 4; o > 0; o >>= 1) s += __shfl_xor_sync(0xffu, s, o);
        if (threadIdx.x == 0) {
            float d = (s > 0.f) ? rsqrtf(s) : 0.f;
            g_dis[row] = d;
            sdis = d;
        }
    }
    __syncthreads();
    float d = sdis;
    __half2* oh = (__half2*)(g_Ah + (size_t)row * NN);
    for (int i = threadIdx.x; i < NN / 4; i += 256) {
        float4 v = p[i];
        oh[2 * i]     = __floats2half2_rn(v.x * d, v.y * d);
        oh[2 * i + 1] = __floats2half2_rn(v.z * d, v.w * d);
    }
}

// tf32 W1 (k->n) + fp16 W2^T, W3^T ([fo][fi])
__global__ void k_prepW(const float* __restrict__ W1, const float* __restrict__ W2,
                        const float* __restrict__ W3) {
    int i = blockIdx.x * 256 + threadIdx.x;
    const float* W = (i < FD * FD) ? W1 : (i < 2 * FD * FD ? W2 : W3);
    int j = i & (FD * FD - 1);
    g_Wr[i] = __uint_as_float(cvt_rna(W[j]));
    if (i >= FD * FD) {
        int l = (i < 2 * FD * FD) ? 0 : 1;
        int fo = j >> 7, fi = j & 127;
        g_Wh[l][fo * FD + fi] = __float2half_rn(W[fi * FD + fo]);
    }
}

// ---------------- small GEMM (tf32), layer 0: H1 = dis*lrelu(X@W1+b1) -> g_HhA ----
// 256 CTAs x 256 threads, CTA tile 64x128 -> 2 CTAs/SM, one full wave.
#define KC 32
#define SSTG 4
#define APAD 36
#define BPAD 136
#define A_TILE_F (64 * APAD)               // 2304 floats
#define B_TILE_F (KC * BPAD)               // 4352 floats
#define STAGE_F  (A_TILE_F + B_TILE_F)     // 6656 floats
#define SMALL_SMEM (SSTG * STAGE_F * 4)    // 106496 B (x2 CTAs = 212992 <= 232448)
#define NTS 256

__global__ __launch_bounds__(NTS, 2) void k_small(
    const float* __restrict__ Xext, const float* __restrict__ bias)
{
    extern __shared__ float sm[];
    int tid = threadIdx.x, lane = tid & 31, warp = tid >> 5;
    int warpM = (warp & 1) * 32, warpN = (warp >> 1) * 32;   // 2M x 4N
    int grow = blockIdx.x * 64;
    const float* A = Xext + (size_t)grow * FD;
    const float* B = g_Wr;

    float acc[2][4][4];
    #pragma unroll
    for (int mt = 0; mt < 2; mt++)
        #pragma unroll
        for (int nt = 0; nt < 4; nt++)
            #pragma unroll
            for (int i = 0; i < 4; i++) acc[mt][nt][i] = 0.f;

    auto issue = [&](int chunk) {
        float* as = sm + (chunk % SSTG) * STAGE_F;
        float* bs = as + A_TILE_F;
        uint32_t as_u = (uint32_t)__cvta_generic_to_shared(as);
        uint32_t bs_u = (uint32_t)__cvta_generic_to_shared(bs);
        int kbase = chunk * KC;
        #pragma unroll
        for (int j = 0; j < 2; j++) {                  // A: 64x32 floats = 512 f4
            int i = tid + NTS * j;
            int r = i >> 3, c = (i & 7) << 2;
            cp16(as_u + (uint32_t)(r * APAD + c) * 4, A + (size_t)r * FD + kbase + c);
        }
        #pragma unroll
        for (int j = 0; j < 4; j++) {                  // B: 32x128 floats = 1024 f4
            int i = tid + NTS * j;
            int k = i >> 5, c = (i & 31) << 2;
            cp16(bs_u + (uint32_t)(k * BPAD + c) * 4, B + (size_t)(kbase + k) * FD + c);
        }
        asm volatile("cp.async.commit_group;");
    };

    int nch = FD / KC;                                 // 4
    #pragma unroll
    for (int p = 0; p < SSTG - 1; p++)
        if (p < nch) issue(p);

    for (int ch = 0; ch < nch; ch++) {
        asm volatile("cp.async.wait_group %0;" :: "n"(SSTG - 2));
        __syncthreads();
        if (ch + SSTG - 1 < nch) issue(ch + SSTG - 1);
        else asm volatile("cp.async.commit_group;");

        float* as = sm + (ch % SSTG) * STAGE_F;
        float* bs = as + A_TILE_F;
        #pragma unroll
        for (int kk = 0; kk < 4; kk++) {
            int kof = kk * 8;
            uint32_t af[2][4];
            uint32_t bf[4][2];
            #pragma unroll
            for (int mt = 0; mt < 2; mt++) {
                int r0 = warpM + mt * 16 + (lane >> 2);
                int kc = kof + (lane & 3);
                af[mt][0] = cvt_rna(as[r0 * APAD + kc]);
                af[mt][1] = cvt_rna(as[(r0 + 8) * APAD + kc]);
                af[mt][2] = cvt_rna(as[r0 * APAD + kc + 4]);
                af[mt][3] = cvt_rna(as[(r0 + 8) * APAD + kc + 4]);
            }
            #pragma unroll
            for (int nt = 0; nt < 4; nt++) {
                int nc = warpN + nt * 8 + (lane >> 2);
                int kr = kof + (lane & 3);
                bf[nt][0] = __float_as_uint(bs[kr * BPAD + nc]);
                bf[nt][1] = __float_as_uint(bs[(kr + 4) * BPAD + nc]);
            }
            #pragma unroll
            for (int mt = 0; mt < 2; mt++)
                #pragma unroll
                for (int nt = 0; nt < 4; nt++)
                    mma8(acc[mt][nt], af[mt], bf[nt]);
        }
    }

    #pragma unroll
    for (int mt = 0; mt < 2; mt++) {
        #pragma unroll
        for (int nt = 0; nt < 4; nt++) {
            int r0 = grow + warpM + mt * 16 + (lane >> 2);
            int n0 = warpN + nt * 8 + 2 * (lane & 3);
            #pragma unroll
            for (int i = 0; i < 4; i++) {
                int r = r0 + ((i >= 2) ? 8 : 0);
                int n = n0 + (i & 1);
                float v = acc[mt][nt][i];
                v += bias[n];
                v = (v > 0.f) ? v : 0.01f * v;
                v *= g_dis[r];
                int b = r >> 11, m = r & (NN - 1);
                g_HhA[((size_t)b * FD + n) * NN + m] = __float2half_rn(v);
            }
        }
    }
}

// ---------------- fused big GEMM (proven best config, rounds 10/15) ----------------
// Z = (dis*adj)@H (+X1 if layer==1). layer<2: H_next = fp16(dis*lrelu(Z@W+b)) fused.
// KCB=128 chunks stored as two 16KB SW128 k-blocks per operand; 1 barrier/chunk.
#define KCB 128
#define BSTG 3
#define STAGE 65536                        // A (2x16KB) + B (2x16KB)
#define WT_OFF (BSTG * STAGE)              // 196608, W^T 32 KB
#define HT_OFF 65536                       // Ht reuses stage-1 region post-mainloop
#define HT_PITCH 272
#define BIG_SMEM (WT_OFF + 32768)          // 229376 <= 232448

__global__ __launch_bounds__(512, 1) void k_big(
    const float* __restrict__ bias_next, float* __restrict__ outext, int layer)
{
    extern __shared__ char smc[];
    uint32_t smb = (uint32_t)__cvta_generic_to_shared(smc);
    int tid = threadIdx.x, lane = tid & 31, warp = tid >> 5;
    int warpM = (warp & 3) * 32, warpN = (warp >> 2) * 32;
    int b = blockIdx.y;
    int mloc = blockIdx.x * 128;
    int grow = b * NN + mloc;

    const __half* Ah = g_Ah + (size_t)grow * NN;
    const __half* Bh = (layer == 1 ? g_HhB : g_HhA) + (size_t)b * FD * NN;
    __half* Hout = (layer == 0) ? g_HhB : g_HhA;

    float acc[2][4][4];
    #pragma unroll
    for (int mt = 0; mt < 2; mt++)
        #pragma unroll
        for (int nt = 0; nt < 4; nt++)
            #pragma unroll
            for (int i = 0; i < 4; i++) acc[mt][nt][i] = 0.f;

    // W^T preload (fp16 [fo][fi], two 64-fi 16KB k-blocks, SW128)
    if (layer < 2) {
        const __half* Wg = g_Wh[layer];
        #pragma unroll
        for (int j = 0; j < 4; j++) {
            int i = tid + 512 * j;
            int blk = i >> 10;
            int r = (i >> 3) & 127, c = i & 7;
            cp16(smb + WT_OFF + blk * 16384 + SWZ128((uint32_t)(r * 128 + c * 16)),
                 (const char*)(Wg + (size_t)r * FD + blk * 64) + c * 16);
        }
        asm volatile("cp.async.commit_group;");
    }

    auto issue = [&](int ch) {
        uint32_t base = smb + (ch % BSTG) * STAGE;
        int kb = ch * KCB;
        #pragma unroll
        for (int j = 0; j < 4; j++) {             // 2048 16B segs per operand
            int i = tid + 512 * j;
            int blk = i >> 10;                    // k-half 0/1
            int rr = (i >> 3) & 127, c = i & 7;
            uint32_t dsw = (uint32_t)(blk * 16384) + SWZ128((uint32_t)(rr * 128 + c * 16));
            size_t so = (size_t)rr * NN + kb + blk * 64 + c * 8;
            cp16(base + dsw,         Ah + so);
            cp16(base + 32768 + dsw, Bh + so);
        }
        asm volatile("cp.async.commit_group;");
    };

    const int nch = NN / KCB;                     // 16
    issue(0); issue(1);

    int mat = lane >> 3;
    for (int ch = 0; ch < nch; ch++) {
        asm volatile("cp.async.wait_group 1;");
        __syncthreads();
        if (ch + 2 < nch) issue(ch + 2);
        else asm volatile("cp.async.commit_group;");   // exact wait_group bound in tail

        uint32_t base = smb + (ch % BSTG) * STAGE;
        #pragma unroll
        for (int s = 0; s < 8; s++) {             // eight K=16 steps per chunk
            uint32_t blkoff = (uint32_t)((s >> 2) * 16384);
            uint32_t cbase = (uint32_t)((s & 3) * 32);
            uint32_t ah[2][4];
            #pragma unroll
            for (int mt = 0; mt < 2; mt++) {
                int row = warpM + mt * 16 + ((mat & 1) << 3) + (lane & 7);
                uint32_t col = cbase + ((mat >> 1) << 4);
                LDSM4(ah[mt], base + blkoff + SWZ128((uint32_t)(row * 128) + col));
            }
            uint32_t bf[4][2];
            #pragma unroll
            for (int p = 0; p < 2; p++) {
                int nrow = warpN + (p * 2 + (mat >> 1)) * 8 + (lane & 7);
                uint32_t col = cbase + ((mat & 1) << 4);
                uint32_t t[4];
                LDSM4(t, base + 32768 + blkoff + SWZ128((uint32_t)(nrow * 128) + col));
                bf[2 * p][0] = t[0]; bf[2 * p][1] = t[1];
                bf[2 * p + 1][0] = t[2]; bf[2 * p + 1][1] = t[3];
            }
            #pragma unroll
            for (int mt = 0; mt < 2; mt++)
                #pragma unroll
                for (int nt = 0; nt < 4; nt++)
                    mma_f16(acc[mt][nt], ah[mt], bf[nt]);
        }
    }

    if (layer == 2) {
        #pragma unroll
        for (int mt = 0; mt < 2; mt++)
            #pragma unroll
            for (int nt = 0; nt < 4; nt++) {
                int r0 = grow + warpM + mt * 16 + (lane >> 2);
                int n = warpN + nt * 8 + 2 * (lane & 3);
                #pragma unroll
                for (int h = 0; h < 2; h++) {
                    int r = r0 + h * 8;
                    float2 v = {acc[mt][nt][h * 2], acc[mt][nt][h * 2 + 1]};
                    *(float2*)(outext + (size_t)r * FD + n) = v;
                }
            }
        return;
    }

    // --- fused epilogue: Z -> stage-0 smem (fp16), small GEMM, H_next ---
    __syncthreads();                         // stage-0 region reuse is safe after this
    #pragma unroll
    for (int mt = 0; mt < 2; mt++)
        #pragma unroll
        for (int nt = 0; nt < 4; nt++) {
            int rl0 = warpM + mt * 16 + (lane >> 2);
            int f = warpN + nt * 8 + 2 * (lane & 3);
            #pragma unroll
            for (int h = 0; h < 2; h++) {
                int rl = rl0 + h * 8;
                float zx = acc[mt][nt][h * 2], zy = acc[mt][nt][h * 2 + 1];
                if (layer == 1) {
                    __half2 rv = *(const __half2*)(g_Xh1 + (size_t)(grow + rl) * FD + f);
                    float2 rf = __half22float2(rv);
                    zx += rf.x; zy += rf.y;
                }
                __half2 hz = __floats2half2_rn(zx, zy);
                uint32_t zo = (uint32_t)((f >> 6) << 14)
                            + SWZ128((uint32_t)(rl * 128 + (f & 63) * 2));
                *(__half2*)(smc + zo) = hz;
                if (layer == 0)
                    *(__half2*)(g_Xh1 + (size_t)(grow + rl) * FD + f) = hz;
            }
        }
    asm volatile("cp.async.wait_group 0;");   // W tile resident
    __syncthreads();

    #pragma unroll
    for (int mt = 0; mt < 2; mt++)
        #pragma unroll
        for (int nt = 0; nt < 4; nt++)
            #pragma unroll
            for (int i = 0; i < 4; i++) acc[mt][nt][i] = 0.f;

    #pragma unroll
    for (int wz = 0; wz < 2; wz++) {
        uint32_t za = smb + wz * 16384;
        uint32_t wa = smb + WT_OFF + wz * 16384;
        #pragma unroll
        for (int s = 0; s < 4; s++) {
            uint32_t ah[2][4];
            #pragma unroll
            for (int mt = 0; mt < 2; mt++) {
                int row = warpM + mt * 16 + ((mat & 1) << 3) + (lane & 7);
                uint32_t col = (uint32_t)(s * 32 + ((mat >> 1) << 4));
                LDSM4(ah[mt], za + SWZ128((uint32_t)(row * 128) + col));
            }
            uint32_t bf[4][2];
            #pragma unroll
            for (int p = 0; p < 2; p++) {
                int nrow = warpN + (p * 2 + (mat >> 1)) * 8 + (lane & 7);
                uint32_t col = (uint32_t)(s * 32 + ((mat & 1) << 4));
                uint32_t t[4];
                LDSM4(t, wa + SWZ128((uint32_t)(nrow * 128) + col));
                bf[2 * p][0] = t[0]; bf[2 * p][1] = t[1];
                bf[2 * p + 1][0] = t[2]; bf[2 * p + 1][1] = t[3];
            }
            #pragma unroll
            for (int mt = 0; mt < 2; mt++)
                #pragma unroll
                for (int nt = 0; nt < 4; nt++)
                    mma_f16(acc[mt][nt], ah[mt], bf[nt]);
        }
    }

    // epilogue2: H = fp16(dis * lrelu(acc + bias)) -> Ht smem [f][m]
    #pragma unroll
    for (int mt = 0; mt < 2; mt++)
        #pragma unroll
        for (int nt = 0; nt < 4; nt++) {
            int rl0 = warpM + mt * 16 + (lane >> 2);
            int f = warpN + nt * 8 + 2 * (lane & 3);
            float bx = bias_next[f], by = bias_next[f + 1];
            #pragma unroll
            for (int h = 0; h < 2; h++) {
                int rl = rl0 + h * 8;
                float d = g_dis[grow + rl];
                float vx = acc[mt][nt][h * 2] + bx;
                float vy = acc[mt][nt][h * 2 + 1] + by;
                vx = (vx > 0.f) ? vx : 0.01f * vx;
                vy = (vy > 0.f) ? vy : 0.01f * vy;
                *(__half*)(smc + HT_OFF + f * HT_PITCH + rl * 2) = __float2half_rn(vx * d);
                *(__half*)(smc + HT_OFF + (f + 1) * HT_PITCH + rl * 2) = __float2half_rn(vy * d);
            }
        }
    __syncthreads();

    {
        int f = tid >> 2, seg = tid & 3;
        const char* src = smc + HT_OFF + f * HT_PITCH + seg * 64;
        __half* dst = Hout + ((size_t)b * FD + f) * NN + mloc + seg * 32;
        #pragma unroll
        for (int j = 0; j < 4; j++)
            *(float4*)(dst + j * 8) = *(const float4*)(src + j * 16);
    }
}

// ---------------- launch ----------------
extern "C" void kernel_launch(void* const* d_in, const int* in_sizes, int n_in,
                              void* d_out, int out_size) {
    (void)in_sizes; (void)n_in; (void)out_size;
    const float* X   = (const float*)d_in[0];
    const float* adj = (const float*)d_in[1];
    const float* W1  = (const float*)d_in[2];
    const float* b1  = (const float*)d_in[3];
    const float* W2  = (const float*)d_in[4];
    const float* b2  = (const float*)d_in[5];
    const float* W3  = (const float*)d_in[6];
    const float* b3  = (const float*)d_in[7];
    float* out = (float*)d_out;

    cudaFuncSetAttribute(k_small, cudaFuncAttributeMaxDynamicSharedMemorySize, SMALL_SMEM);
    cudaFuncSetAttribute(k_big,   cudaFuncAttributeMaxDynamicSharedMemorySize, BIG_SMEM);

    k_prep<<<NB * NN, 256>>>(adj);
    k_prepW<<<(3 * FD * FD) / 256, 256>>>(W1, W2, W3);

    k_small<<<16384 / 64, NTS, SMALL_SMEM>>>(X, b1);           // H1 -> g_HhA
    k_big<<<dim3(16, NB), 512, BIG_SMEM>>>(b2, out, 0);        // Z1, H2 -> g_HhB, X1
    k_big<<<dim3(16, NB), 512, BIG_SMEM>>>(b3, out, 1);        // Z2(+X1), H3 -> g_HhA
    k_big<<<dim3(16, NB), 512, BIG_SMEM>>>(b1, out, 2);        // out = A'@H3
}

// round 17
// speedup vs baseline: 1.6434x; 1.6434x over previous
#include <cuda_runtime.h>
#include <cuda_fp16.h>
#include <cstdint>
#include <cstddef>

#define NB 8
#define NN 2048
#define FD 128

// ---------------- device scratch (no cudaMalloc allowed) ----------------
__device__ float g_dis[NB * NN];
__device__ __half g_Ah[(size_t)NB * NN * NN];   // fp16(dis[n]*adj[n,m])
__device__ __half g_HhA[NB * FD * NN];          // H transposed [b][f][m], buffer A
__device__ __half g_HhB[NB * FD * NN];          // buffer B
__device__ __half g_Xh1[NB * NN * FD];          // fp16 X1 (for residual)
__device__ float g_Wr[3 * FD * FD];             // tf32 weights (layer-0 small GEMM)
__device__ __half g_Wh[2][FD * FD];             // fp16 W^T for W2, W3: [fo][fi]

// ---------------- helpers ----------------
__device__ __forceinline__ uint32_t cvt_rna(float x) {
    uint32_t r;
    asm("cvt.rna.tf32.f32 %0, %1;" : "=r"(r) : "f"(x));
    return r;
}
__device__ __forceinline__ void cp16(uint32_t smem_dst, const void* gsrc) {
    asm volatile("cp.async.cg.shared.global [%0], [%1], 16;" :: "r"(smem_dst), "l"(gsrc));
}
#define SWZ128(o) ((o) ^ (((o) >> 3) & 0x70))

#define LDSM4(R, a) \
    asm volatile("ldmatrix.sync.aligned.m8n8.x4.shared.b16 {%0,%1,%2,%3}, [%4];" \
        : "=r"((R)[0]), "=r"((R)[1]), "=r"((R)[2]), "=r"((R)[3]) : "r"(a))

__device__ __forceinline__ void mma_f16(float* c, const uint32_t* a, const uint32_t* b) {
    asm volatile(
        "mma.sync.aligned.m16n8k16.row.col.f32.f16.f16.f32 "
        "{%0,%1,%2,%3}, {%4,%5,%6,%7}, {%8,%9}, {%0,%1,%2,%3};"
        : "+f"(c[0]), "+f"(c[1]), "+f"(c[2]), "+f"(c[3])
        : "r"(a[0]), "r"(a[1]), "r"(a[2]), "r"(a[3]), "r"(b[0]), "r"(b[1]));
}
__device__ __forceinline__ void mma8(float* c, const uint32_t* a, const uint32_t* b) {
    asm volatile(
        "mma.sync.aligned.m16n8k8.row.col.f32.tf32.tf32.f32 "
        "{%0,%1,%2,%3}, {%4,%5,%6,%7}, {%8,%9}, {%0,%1,%2,%3};"
        : "+f"(c[0]), "+f"(c[1]), "+f"(c[2]), "+f"(c[3])
        : "r"(a[0]), "r"(a[1]), "r"(a[2]), "r"(a[3]), "r"(b[0]), "r"(b[1]));
}

// ---------------- prep: rowsum -> dis -> write fp16 dis*adj ----------------
__global__ void k_prep(const float* __restrict__ adj) {
    __shared__ float red[8];
    __shared__ float sdis;
    int row = blockIdx.x;
    const float4* p = (const float4*)(adj + (size_t)row * NN);
    float s = 0.f;
    for (int i = threadIdx.x; i < NN / 4; i += 256) {
        float4 v = p[i];
        s += (v.x + v.y) + (v.z + v.w);
    }
    #pragma unroll
    for (int o = 16; o > 0; o >>= 1) s += __shfl_xor_sync(0xffffffffu, s, o);
    if ((threadIdx.x & 31) == 0) red[threadIdx.x >> 5] = s;
    __syncthreads();
    if (threadIdx.x < 8) {
        s = red[threadIdx.x];
        #pragma unroll
        for (int o = 4; o > 0; o >>= 1) s += __shfl_xor_sync(0xffu, s, o);
        if (threadIdx.x == 0) {
            float d = (s > 0.f) ? rsqrtf(s) : 0.f;
            g_dis[row] = d;
            sdis = d;
        }
    }
    __syncthreads();
    float d = sdis;
    __half2* oh = (__half2*)(g_Ah + (size_t)row * NN);
    for (int i = threadIdx.x; i < NN / 4; i += 256) {
        float4 v = p[i];
        oh[2 * i]     = __floats2half2_rn(v.x * d, v.y * d);
        oh[2 * i + 1] = __floats2half2_rn(v.z * d, v.w * d);
    }
}

// tf32 W1 (k->n) + fp16 W2^T, W3^T ([fo][fi])
__global__ void k_prepW(const float* __restrict__ W1, const float* __restrict__ W2,
                        const float* __restrict__ W3) {
    int i = blockIdx.x * 256 + threadIdx.x;
    const float* W = (i < FD * FD) ? W1 : (i < 2 * FD * FD ? W2 : W3);
    int j = i & (FD * FD - 1);
    g_Wr[i] = __uint_as_float(cvt_rna(W[j]));
    if (i >= FD * FD) {
        int l = (i < 2 * FD * FD) ? 0 : 1;
        int fo = j >> 7, fi = j & 127;
        g_Wh[l][fo * FD + fi] = __float2half_rn(W[fi * FD + fo]);
    }
}

// ---------------- small GEMM (tf32), layer 0: H1 = dis*lrelu(X@W1+b1) -> g_HhA ----
// 256 CTAs x 256 threads, CTA tile 64x128 -> 2 CTAs/SM, one full wave.
#define KC 32
#define SSTG 4
#define APAD 36
#define BPAD 136
#define A_TILE_F (64 * APAD)               // 2304 floats
#define B_TILE_F (KC * BPAD)               // 4352 floats
#define STAGE_F  (A_TILE_F + B_TILE_F)     // 6656 floats
#define SMALL_SMEM (SSTG * STAGE_F * 4)    // 106496 B (x2 CTAs = 212992 <= 232448)
#define NTS 256

__global__ __launch_bounds__(NTS, 2) void k_small(
    const float* __restrict__ Xext, const float* __restrict__ bias)
{
    extern __shared__ float sm[];
    int tid = threadIdx.x, lane = tid & 31, warp = tid >> 5;
    int warpM = (warp & 1) * 32, warpN = (warp >> 1) * 32;   // 2M x 4N
    int grow = blockIdx.x * 64;
    const float* A = Xext + (size_t)grow * FD;
    const float* B = g_Wr;

    float acc[2][4][4];
    #pragma unroll
    for (int mt = 0; mt < 2; mt++)
        #pragma unroll
        for (int nt = 0; nt < 4; nt++)
            #pragma unroll
            for (int i = 0; i < 4; i++) acc[mt][nt][i] = 0.f;

    auto issue = [&](int chunk) {
        float* as = sm + (chunk % SSTG) * STAGE_F;
        float* bs = as + A_TILE_F;
        uint32_t as_u = (uint32_t)__cvta_generic_to_shared(as);
        uint32_t bs_u = (uint32_t)__cvta_generic_to_shared(bs);
        int kbase = chunk * KC;
        #pragma unroll
        for (int j = 0; j < 2; j++) {                  // A: 64x32 floats = 512 f4
            int i = tid + NTS * j;
            int r = i >> 3, c = (i & 7) << 2;
            cp16(as_u + (uint32_t)(r * APAD + c) * 4, A + (size_t)r * FD + kbase + c);
        }
        #pragma unroll
        for (int j = 0; j < 4; j++) {                  // B: 32x128 floats = 1024 f4
            int i = tid + NTS * j;
            int k = i >> 5, c = (i & 31) << 2;
            cp16(bs_u + (uint32_t)(k * BPAD + c) * 4, B + (size_t)(kbase + k) * FD + c);
        }
        asm volatile("cp.async.commit_group;");
    };

    int nch = FD / KC;                                 // 4
    #pragma unroll
    for (int p = 0; p < SSTG - 1; p++)
        if (p < nch) issue(p);

    for (int ch = 0; ch < nch; ch++) {
        asm volatile("cp.async.wait_group %0;" :: "n"(SSTG - 2));
        __syncthreads();
        if (ch + SSTG - 1 < nch) issue(ch + SSTG - 1);
        else asm volatile("cp.async.commit_group;");

        float* as = sm + (ch % SSTG) * STAGE_F;
        float* bs = as + A_TILE_F;
        #pragma unroll
        for (int kk = 0; kk < 4; kk++) {
            int kof = kk * 8;
            uint32_t af[2][4];
            uint32_t bf[4][2];
            #pragma unroll
            for (int mt = 0; mt < 2; mt++) {
                int r0 = warpM + mt * 16 + (lane >> 2);
                int kc = kof + (lane & 3);
                af[mt][0] = cvt_rna(as[r0 * APAD + kc]);
                af[mt][1] = cvt_rna(as[(r0 + 8) * APAD + kc]);
                af[mt][2] = cvt_rna(as[r0 * APAD + kc + 4]);
                af[mt][3] = cvt_rna(as[(r0 + 8) * APAD + kc + 4]);
            }
            #pragma unroll
            for (int nt = 0; nt < 4; nt++) {
                int nc = warpN + nt * 8 + (lane >> 2);
                int kr = kof + (lane & 3);
                bf[nt][0] = __float_as_uint(bs[kr * BPAD + nc]);
                bf[nt][1] = __float_as_uint(bs[(kr + 4) * BPAD + nc]);
            }
            #pragma unroll
            for (int mt = 0; mt < 2; mt++)
                #pragma unroll
                for (int nt = 0; nt < 4; nt++)
                    mma8(acc[mt][nt], af[mt], bf[nt]);
        }
    }

    #pragma unroll
    for (int mt = 0; mt < 2; mt++) {
        #pragma unroll
        for (int nt = 0; nt < 4; nt++) {
            int r0 = grow + warpM + mt * 16 + (lane >> 2);
            int n0 = warpN + nt * 8 + 2 * (lane & 3);
            #pragma unroll
            for (int i = 0; i < 4; i++) {
                int r = r0 + ((i >= 2) ? 8 : 0);
                int n = n0 + (i & 1);
                float v = acc[mt][nt][i];
                v += bias[n];
                v = (v > 0.f) ? v : 0.01f * v;
                v *= g_dis[r];
                int b = r >> 11, m = r & (NN - 1);
                g_HhA[((size_t)b * FD + n) * NN + m] = __float2half_rn(v);
            }
        }
    }
}

// ---------------- fused big GEMM (proven best config) ----------------
// Z = (dis*adj)@H (+X1 if layer==1). layer<2: H_next = fp16(dis*lrelu(Z@W+b)) fused.
// KCB=128 chunks stored as two 16KB SW128 k-blocks per operand; 1 barrier/chunk.
#define KCB 128
#define BSTG 3
#define STAGE 65536                        // A (2x16KB) + B (2x16KB)
#define WT_OFF (BSTG * STAGE)              // 196608, W^T 32 KB
#define HT_OFF 65536                       // Ht reuses stage-1 region post-mainloop
#define HT_PITCH 272
#define BIG_SMEM (WT_OFF + 32768)          // 229376 <= 232448

__global__ __launch_bounds__(512, 1) void k_big(
    const float* __restrict__ bias_next, float* __restrict__ outext, int layer)
{
    extern __shared__ char smc[];
    uint32_t smb = (uint32_t)__cvta_generic_to_shared(smc);
    int tid = threadIdx.x, lane = tid & 31, warp = tid >> 5;
    int warpM = (warp & 3) * 32, warpN = (warp >> 2) * 32;
    int b = blockIdx.y;
    int mloc = blockIdx.x * 128;
    int grow = b * NN + mloc;

    const __half* Ah = g_Ah + (size_t)grow * NN;
    const __half* Bh = (layer == 1 ? g_HhB : g_HhA) + (size_t)b * FD * NN;
    __half* Hout = (layer == 0) ? g_HhB : g_HhA;

    float acc[2][4][4];
    #pragma unroll
    for (int mt = 0; mt < 2; mt++)
        #pragma unroll
        for (int nt = 0; nt < 4; nt++)
            #pragma unroll
            for (int i = 0; i < 4; i++) acc[mt][nt][i] = 0.f;

    // W^T preload (fp16 [fo][fi], two 64-fi 16KB k-blocks, SW128)
    if (layer < 2) {
        const __half* Wg = g_Wh[layer];
        #pragma unroll
        for (int j = 0; j < 4; j++) {
            int i = tid + 512 * j;
            int blk = i >> 10;
            int r = (i >> 3) & 127, c = i & 7;
            cp16(smb + WT_OFF + blk * 16384 + SWZ128((uint32_t)(r * 128 + c * 16)),
                 (const char*)(Wg + (size_t)r * FD + blk * 64) + c * 16);
        }
        asm volatile("cp.async.commit_group;");
    }

    auto issue = [&](int ch) {
        uint32_t base = smb + (ch % BSTG) * STAGE;
        int kb = ch * KCB;
        #pragma unroll
        for (int j = 0; j < 4; j++) {             // 2048 16B segs per operand
            int i = tid + 512 * j;
            int blk = i >> 10;                    // k-half 0/1
            int rr = (i >> 3) & 127, c = i & 7;
            uint32_t dsw = (uint32_t)(blk * 16384) + SWZ128((uint32_t)(rr * 128 + c * 16));
            size_t so = (size_t)rr * NN + kb + blk * 64 + c * 8;
            cp16(base + dsw,         Ah + so);
            cp16(base + 32768 + dsw, Bh + so);
        }
        asm volatile("cp.async.commit_group;");
    };

    const int nch = NN / KCB;                     // 16
    issue(0); issue(1);

    int mat = lane >> 3;
    for (int ch = 0; ch < nch; ch++) {
        asm volatile("cp.async.wait_group 1;");
        __syncthreads();
        if (ch + 2 < nch) issue(ch + 2);
        else asm volatile("cp.async.commit_group;");   // exact wait_group bound in tail

        uint32_t base = smb + (ch % BSTG) * STAGE;
        #pragma unroll
        for (int s = 0; s < 8; s++) {             // eight K=16 steps per chunk
            uint32_t blkoff = (uint32_t)((s >> 2) * 16384);
            uint32_t cbase = (uint32_t)((s & 3) * 32);
            uint32_t ah[2][4];
            #pragma unroll
            for (int mt = 0; mt < 2; mt++) {
                int row = warpM + mt * 16 + ((mat & 1) << 3) + (lane & 7);
                uint32_t col = cbase + ((mat >> 1) << 4);
                LDSM4(ah[mt], base + blkoff + SWZ128((uint32_t)(row * 128) + col));
            }
            uint32_t bf[4][2];
            #pragma unroll
            for (int p = 0; p < 2; p++) {
                int nrow = warpN + (p * 2 + (mat >> 1)) * 8 + (lane & 7);
                uint32_t col = cbase + ((mat & 1) << 4);
                uint32_t t[4];
                LDSM4(t, base + 32768 + blkoff + SWZ128((uint32_t)(nrow * 128) + col));
                bf[2 * p][0] = t[0]; bf[2 * p][1] = t[1];
                bf[2 * p + 1][0] = t[2]; bf[2 * p + 1][1] = t[3];
            }
            #pragma unroll
            for (int mt = 0; mt < 2; mt++)
                #pragma unroll
                for (int nt = 0; nt < 4; nt++)
                    mma_f16(acc[mt][nt], ah[mt], bf[nt]);
        }
    }

    if (layer == 2) {
        #pragma unroll
        for (int mt = 0; mt < 2; mt++)
            #pragma unroll
            for (int nt = 0; nt < 4; nt++) {
                int r0 = grow + warpM + mt * 16 + (lane >> 2);
                int n = warpN + nt * 8 + 2 * (lane & 3);
                #pragma unroll
                for (int h = 0; h < 2; h++) {
                    int r = r0 + h * 8;
                    float2 v = {acc[mt][nt][h * 2], acc[mt][nt][h * 2 + 1]};
                    *(float2*)(outext + (size_t)r * FD + n) = v;
                }
            }
        return;
    }

    // --- fused epilogue: Z -> stage-0 smem (fp16), small GEMM, H_next ---
    __syncthreads();                         // stage-0 region reuse is safe after this
    #pragma unroll
    for (int mt = 0; mt < 2; mt++)
        #pragma unroll
        for (int nt = 0; nt < 4; nt++) {
            int rl0 = warpM + mt * 16 + (lane >> 2);
            int f = warpN + nt * 8 + 2 * (lane & 3);
            #pragma unroll
            for (int h = 0; h < 2; h++) {
                int rl = rl0 + h * 8;
                float zx = acc[mt][nt][h * 2], zy = acc[mt][nt][h * 2 + 1];
                if (layer == 1) {
                    __half2 rv = *(const __half2*)(g_Xh1 + (size_t)(grow + rl) * FD + f);
                    float2 rf = __half22float2(rv);
                    zx += rf.x; zy += rf.y;
                }
                __half2 hz = __floats2half2_rn(zx, zy);
                uint32_t zo = (uint32_t)((f >> 6) << 14)
                            + SWZ128((uint32_t)(rl * 128 + (f & 63) * 2));
                *(__half2*)(smc + zo) = hz;
                if (layer == 0)
                    *(__half2*)(g_Xh1 + (size_t)(grow + rl) * FD + f) = hz;
            }
        }
    asm volatile("cp.async.wait_group 0;");   // W tile resident
    __syncthreads();

    #pragma unroll
    for (int mt = 0; mt < 2; mt++)
        #pragma unroll
        for (int nt = 0; nt < 4; nt++)
            #pragma unroll
            for (int i = 0; i < 4; i++) acc[mt][nt][i] = 0.f;

    #pragma unroll
    for (int wz = 0; wz < 2; wz++) {
        uint32_t za = smb + wz * 16384;
        uint32_t wa = smb + WT_OFF + wz * 16384;
        #pragma unroll
        for (int s = 0; s < 4; s++) {
            uint32_t ah[2][4];
            #pragma unroll
            for (int mt = 0; mt < 2; mt++) {
                int row = warpM + mt * 16 + ((mat & 1) << 3) + (lane & 7);
                uint32_t col = (uint32_t)(s * 32 + ((mat >> 1) << 4));
                LDSM4(ah[mt], za + SWZ128((uint32_t)(row * 128) + col));
            }
            uint32_t bf[4][2];
            #pragma unroll
            for (int p = 0; p < 2; p++) {
                int nrow = warpN + (p * 2 + (mat >> 1)) * 8 + (lane & 7);
                uint32_t col = (uint32_t)(s * 32 + ((mat & 1) << 4));
                uint32_t t[4];
                LDSM4(t, wa + SWZ128((uint32_t)(nrow * 128) + col));
                bf[2 * p][0] = t[0]; bf[2 * p][1] = t[1];
                bf[2 * p + 1][0] = t[2]; bf[2 * p + 1][1] = t[3];
            }
            #pragma unroll
            for (int mt = 0; mt < 2; mt++)
                #pragma unroll
                for (int nt = 0; nt < 4; nt++)
                    mma_f16(acc[mt][nt], ah[mt], bf[nt]);
        }
    }

    // epilogue2: H = fp16(dis * lrelu(acc + bias)) -> Ht smem [f][m]
    #pragma unroll
    for (int mt = 0; mt < 2; mt++)
        #pragma unroll
        for (int nt = 0; nt < 4; nt++) {
            int rl0 = warpM + mt * 16 + (lane >> 2);
            int f = warpN + nt * 8 + 2 * (lane & 3);
            float bx = bias_next[f], by = bias_next[f + 1];
            #pragma unroll
            for (int h = 0; h < 2; h++) {
                int rl = rl0 + h * 8;
                float d = g_dis[grow + rl];
                float vx = acc[mt][nt][h * 2] + bx;
                float vy = acc[mt][nt][h * 2 + 1] + by;
                vx = (vx > 0.f) ? vx : 0.01f * vx;
                vy = (vy > 0.f) ? vy : 0.01f * vy;
                *(__half*)(smc + HT_OFF + f * HT_PITCH + rl * 2) = __float2half_rn(vx * d);
                *(__half*)(smc + HT_OFF + (f + 1) * HT_PITCH + rl * 2) = __float2half_rn(vy * d);
            }
        }
    __syncthreads();

    {
        int f = tid >> 2, seg = tid & 3;
        const char* src = smc + HT_OFF + f * HT_PITCH + seg * 64;
        __half* dst = Hout + ((size_t)b * FD + f) * NN + mloc + seg * 32;
        #pragma unroll
        for (int j = 0; j < 4; j++)
            *(float4*)(dst + j * 8) = *(const float4*)(src + j * 16);
    }
}

// ---------------- launch ----------------
extern "C" void kernel_launch(void* const* d_in, const int* in_sizes, int n_in,
                              void* d_out, int out_size) {
    (void)in_sizes; (void)n_in; (void)out_size;
    const float* X   = (const float*)d_in[0];
    const float* adj = (const float*)d_in[1];
    const float* W1  = (const float*)d_in[2];
    const float* b1  = (const float*)d_in[3];
    const float* W2  = (const float*)d_in[4];
    const float* b2  = (const float*)d_in[5];
    const float* W3  = (const float*)d_in[6];
    const float* b3  = (const float*)d_in[7];
    float* out = (float*)d_out;

    cudaFuncSetAttribute(k_small, cudaFuncAttributeMaxDynamicSharedMemorySize, SMALL_SMEM);
    cudaFuncSetAttribute(k_big,   cudaFuncAttributeMaxDynamicSharedMemorySize, BIG_SMEM);

    k_prep<<<NB * NN, 256>>>(adj);
    k_prepW<<<(3 * FD * FD) / 256, 256>>>(W1, W2, W3);

    k_small<<<16384 / 64, NTS, SMALL_SMEM>>>(X, b1);           // H1 -> g_HhA
    k_big<<<dim3(16, NB), 512, BIG_SMEM>>>(b2, out, 0);        // Z1, H2 -> g_HhB, X1
    k_big<<<dim3(16, NB), 512, BIG_SMEM>>>(b3, out, 1);        // Z2(+X1), H3 -> g_HhA
    k_big<<<dim3(16, NB), 512, BIG_SMEM>>>(b1, out, 2);        // out = A'@H3
}